// round 11
// baseline (speedup 1.0000x reference)
#include <cuda_runtime.h>
#include <cstdint>
#include <cstddef>

#define H 512
#define W 512
#define C 128
#define TI 16
#define TJ 16
// weights smem (fp32): [16 i][16 j][68 t'] where t' = p*8+q + (p>=4 ? 4 : 0)
// (4-word pad between tap halves so the ph lanes land 4 banks apart).
// j-stride 68 (== 4 mod 32), i-stride 16*68=1088 -> pad 1096 (== 8 mod 32).
// Warp weight load: 4 rows x 2 ph -> bank starts 8r+4ph = 8 distinct 4-bank
// groups, chg lanes broadcast: ONE wavefront per LDS.128.
#define WJ 68
#define WI 1096
#define W3_U32 (16 * WI)                  // 17536 u32 = 70.1 KB
// x halo (fp32): [4 chg][23 rows][25 colpad][4 ch]; position = 16 B.
// row stride 100 u32 (== 4 mod 32), chunk 2300 (== 28 mod 32).
// Warp x load: start = 4*(7c + r + 4ph) mod 32 -> every 4-bank group hit by
// exactly 4 lanes: the 512 B access resolves in the minimum 4 wavefronts.
#define XROW 100
#define XCHUNK 2300
#define XS_U32 (4 * XCHUNK)               // 9200 u32 = 36.8 KB
#define SMEM_FLOATS (W3_U32 + XS_U32 + 529 + 256)   // 27521
#define SMEM_BYTES (SMEM_FLOATS * 4)      // 110,084 B -> 2 CTAs/SM

typedef unsigned long long ull;

__device__ __forceinline__ ull pack2(float a, float b) {
    ull r; asm("mov.b64 %0, {%1, %2};" : "=l"(r) : "f"(a), "f"(b)); return r;
}
__device__ __forceinline__ void fma2(ull& d, ull a, ull b) {
    asm("fma.rn.f32x2 %0, %1, %2, %0;" : "+l"(d) : "l"(a), "l"(b));
}
__device__ __forceinline__ float2 unpack2(ull v) {
    float2 f; asm("mov.b64 {%0, %1}, %2;" : "=f"(f.x), "=f"(f.y) : "l"(v)); return f;
}
__device__ __forceinline__ void cp_async16(float* smem_dst, const float* gsrc, bool pred) {
    uint32_t s = (uint32_t)__cvta_generic_to_shared(smem_dst);
    int sz = pred ? 16 : 0;
    asm volatile("cp.async.cg.shared.global [%0], [%1], 16, %2;\n"
                 :: "r"(s), "l"(gsrc), "r"(sz));
}
__device__ __forceinline__ void cp_async4(float* smem_dst, const float* gsrc, bool pred) {
    uint32_t s = (uint32_t)__cvta_generic_to_shared(smem_dst);
    int sz = pred ? 4 : 0;
    asm volatile("cp.async.ca.shared.global [%0], [%1], 4, %2;\n"
                 :: "r"(s), "l"(gsrc), "r"(sz));
}
__device__ __forceinline__ void cp_commit() {
    asm volatile("cp.async.commit_group;\n" ::: "memory");
}
template <int N> __device__ __forceinline__ void cp_wait() {
    asm volatile("cp.async.wait_group %0;\n" :: "n"(N) : "memory");
}

// weight smem offset for tap (p,q)
__device__ __host__ __forceinline__ int woff(int p, int q) {
    return p * 8 + q + (p >= 4 ? 4 : 0);
}

// ---- stage one 16-channel x pass via cp.async (no cvt, no register trip) ----
__device__ __forceinline__ void stage_x(float* xs, const float* __restrict__ gx,
                                        int bi, int bj, int pass, int tid) {
    const int cbase = pass * 16;
    #pragma unroll 3
    for (int u = tid; u < 529 * 4; u += 256) {
        int q = u & 3, pix = u >> 2;
        int hr = pix / 23, hc = pix - hr * 23;
        int gr = bi + hr - 3, gcl = bj + hc - 3;
        bool ok = ((unsigned)gr < H) && ((unsigned)gcl < W);
        const float* src = ok
            ? gx + (((size_t)gr * W + gcl) * C + cbase + q * 4)
            : gx;
        cp_async16(xs + q * XCHUNK + hr * XROW + hc * 4, src, ok);
    }
}

// ---- compute one pass: 1 row x 8 cols x 4 ch, taps p in [4ph, 4ph+4) ----
__device__ __forceinline__ void compute_pass(const float* __restrict__ xs,
                                             const float* __restrict__ w3,
                                             const float* __restrict__ inv,
                                             float* __restrict__ gout,
                                             int bi, int bj, int cbase,
                                             int row, int j0, int chg, int ph) {
    ull acc[8][2];
    #pragma unroll
    for (int j = 0; j < 8; ++j) { acc[j][0] = 0ull; acc[j][1] = 0ull; }

    const float* xb = xs + chg * XCHUNK + j0 * 4;
    const float* wb = w3 + row * WI + j0 * WJ + ph * 36;

    #pragma unroll
    for (int pp = 0; pp < 4; ++pp) {
        const int xrow = row + ph * 4 + pp;
        // load the 15-position halo row (4 fp32 ch per position, 16 B each)
        ull xf[15][2];
        const ulonglong2* xp = (const ulonglong2*)(xb + xrow * XROW);
        #pragma unroll
        for (int t = 0; t < 15; ++t) {
            ulonglong2 v = xp[t];
            xf[t][0] = v.x; xf[t][1] = v.y;
        }
        #pragma unroll
        for (int j = 0; j < 8; ++j) {
            #pragma unroll
            for (int qg = 0; qg < 2; ++qg) {
                float4 w4 = *(const float4*)(wb + j * WJ + pp * 8 + qg * 4);
                const int t0 = j + qg * 4;
                ull w0 = pack2(w4.x, w4.x);
                ull w1 = pack2(w4.y, w4.y);
                ull w2 = pack2(w4.z, w4.z);
                ull w3p = pack2(w4.w, w4.w);
                fma2(acc[j][0], xf[t0 + 0][0], w0);
                fma2(acc[j][1], xf[t0 + 0][1], w0);
                fma2(acc[j][0], xf[t0 + 1][0], w1);
                fma2(acc[j][1], xf[t0 + 1][1], w1);
                fma2(acc[j][0], xf[t0 + 2][0], w2);
                fma2(acc[j][1], xf[t0 + 2][1], w2);
                fma2(acc[j][0], xf[t0 + 3][0], w3p);
                fma2(acc[j][1], xf[t0 + 3][1], w3p);
            }
        }
    }

    // ---- reduce across ph (lane ^ 4): both halves end with the full sum ----
    float2 sum[8][2];
    #pragma unroll
    for (int j = 0; j < 8; ++j) {
        #pragma unroll
        for (int k = 0; k < 2; ++k) {
            ull o = __shfl_xor_sync(0xffffffffu, acc[j][k], 4);
            float2 a = unpack2(acc[j][k]);
            float2 b = unpack2(o);
            sum[j][k] = make_float2(a.x + b.x, a.y + b.y);
        }
    }
    // ph halves store disjoint j-quarters; 4 chg lanes -> 64 B contiguous
    #pragma unroll
    for (int jl = 0; jl < 4; ++jl) {
        const int j = ph * 4 + jl;
        float s = inv[row * 16 + j0 + j];
        float4 v = make_float4(sum[j][0].x * s, sum[j][0].y * s,
                               sum[j][1].x * s, sum[j][1].y * s);
        *(float4*)(gout + (((size_t)(bi + row) * W + (bj + j0 + j)) * C
                           + cbase + chg * 4)) = v;
    }
}

__global__ __launch_bounds__(256, 2) void cell_att_kernel(
    const float* __restrict__ gx,   // [H][W][C]
    const float* __restrict__ gw,   // [H][W][64]
    const float* __restrict__ gc,   // [H][W]
    float* __restrict__ gout)       // [H][W][C]
{
    extern __shared__ float smem[];
    float* w3  = smem;               // fp32 weights, padded tap layout
    float* xs  = w3 + W3_U32;        // fp32 x halo, 16 channels
    float* ch  = xs + XS_U32;        // 23x23 cnts halo
    float* inv = ch + 529;           // 256 per-pixel 1/(tcnt+1e-6)

    const int tid = threadIdx.x;
    const int chg = tid & 3;            // channel quad (4 ch of 16)
    const int ph  = (tid >> 2) & 1;     // tap half: p in [4ph, 4ph+4)
    const int row = (tid >> 3) & 15;    // 0..15
    const int jg  = tid >> 7;           // 0 or 1 (warp-uniform)
    const int j0  = jg * 8;
    const int bi = blockIdx.y * TI, bj = blockIdx.x * TJ;

    // ---- G0: weights (cp.async into padded layout) + cnts halo ----
    #pragma unroll 8
    for (int u = tid; u < 256 * 16; u += 256) {
        int quad = u & 15, px = u >> 4;
        int il = px >> 4, jl = px & 15;
        const float* src = gw + ((size_t)(bi + il) * W + (bj + jl)) * 64 + quad * 4;
        int dsto = (quad < 8) ? quad * 4 : 36 + (quad - 8) * 4;
        cp_async16(w3 + il * WI + jl * WJ + dsto, src, true);
    }
    for (int u = tid; u < 529; u += 256) {
        int hr = u / 23, hc = u - hr * 23;
        int gr = bi + hr - 3, gcl = bj + hc - 3;
        bool ok = ((unsigned)gr < H) && ((unsigned)gcl < W);
        const float* src = ok ? gc + (size_t)gr * W + gcl : gc;
        cp_async4(ch + u, src, ok);
    }
    cp_commit();                       // G0
    stage_x(xs, gx, bi, bj, 0, tid);
    cp_commit();                       // G1

    cp_wait<1>();                      // G0 done
    __syncthreads();

    // ---- normalizer: inv = 1/(att(cnts)+1e-6), one pixel per thread ----
    {
        int il = tid >> 4, jl = tid & 15;
        const float* wpx = w3 + il * WI + jl * WJ;
        float s = 0.f;
        #pragma unroll
        for (int p = 0; p < 8; ++p)
            #pragma unroll
            for (int q = 0; q < 8; ++q)
                s += ch[(il + p) * 23 + (jl + q)] * wpx[woff(p, q)];
        inv[tid] = 1.0f / (s + 1e-6f);
    }

    cp_wait<0>();                      // G1 (x pass 0) done
    __syncthreads();                   // inv + xs visible
    compute_pass(xs, w3, inv, gout, bi, bj, 0, row, j0, chg, ph);

    #pragma unroll 1
    for (int pass = 1; pass < 8; ++pass) {
        __syncthreads();               // all readers done with xs
        stage_x(xs, gx, bi, bj, pass, tid);
        cp_commit();
        cp_wait<0>();
        __syncthreads();               // new xs visible
        compute_pass(xs, w3, inv, gout, bi, bj, pass * 16, row, j0, chg, ph);
    }
}

extern "C" void kernel_launch(void* const* d_in, const int* in_sizes, int n_in,
                              void* d_out, int out_size) {
    const float* x0 = (const float*)d_in[0];
    const float* w  = (const float*)d_in[1];
    const float* c  = (const float*)d_in[2];
    float* out      = (float*)d_out;
    cudaFuncSetAttribute(cell_att_kernel,
                         cudaFuncAttributeMaxDynamicSharedMemorySize, SMEM_BYTES);
    dim3 grid(W / TJ, H / TI);
    cell_att_kernel<<<grid, 256, SMEM_BYTES>>>(x0, w, c, out);
}